// round 17
// baseline (speedup 1.0000x reference)
#include <cuda_runtime.h>
#include <cstdint>

#define B_ 16
#define N_ 4096
#define M_ 4096
#define D_ 64
#define ROWS_ (B_ * N_)
#define TILE_R 256
#define TILE_N 256
#define NT (M_ / TILE_N)     // 16 code tiles
#define THREADS 256
#define QSCALE 16.0f
#define FILTER 8.0f          // conservative: quant error for near rows <= ~1.5

// ---------------- device globals (no allocation allowed) ----------------
__device__ int      g_hint[M_];            // -round(sum(v^2)/2), v = s8 codes
__device__ uint32_t g_codes_s8[M_ * 16];   // s8 codes, 64 B/row (16 u32)
__device__ int      g_need[ROWS_];         // rows needing exact fallback

__device__ __forceinline__ uint32_t smem_u32(const void* p) {
    uint32_t a;
    asm("{ .reg .u64 t; cvta.to.shared.u64 t, %1; cvt.u32.u64 %0, t; }" : "=r"(a) : "l"(p));
    return a;
}
// 64B-row swizzle (8 rows x 4 chunks of 16B): chunk bits[5:4] ^= row bits[8:7].
// Invariant under +512B (j*8 rows), so per-j addresses are base + j*512.
__device__ __forceinline__ uint32_t swz64(uint32_t o) { return o ^ ((o >> 3) & 0x30); }

__device__ __forceinline__ int clamp8(float v) {
    float q = rintf(v * QSCALE);
    q = fminf(127.f, fmaxf(-127.f, q));
    return (int)q;
}
// pack 4 s32 -> 4 s8 bytes (b0 = i0 ... b3 = i3)
__device__ __forceinline__ uint32_t pack4(int i0, int i1, int i2, int i3) {
    uint32_t hi, r;
    asm("cvt.pack.sat.s8.s32.b32 %0, %1, %2, %3;" : "=r"(hi) : "r"(i3), "r"(i2), "r"(0));
    asm("cvt.pack.sat.s8.s32.b32 %0, %1, %2, %3;" : "=r"(r)  : "r"(i1), "r"(i0), "r"(hi));
    return r;
}
__device__ __forceinline__ uint32_t q4(float4 v) {
    return pack4(clamp8(v.x), clamp8(v.y), clamp8(v.z), clamp8(v.w));
}

#define LDSM4(d0, d1, d2, d3, a)                                                 \
    asm volatile("ldmatrix.sync.aligned.m8n8.x4.shared.b16 {%0,%1,%2,%3}, [%4];" \
        : "=r"(d0), "=r"(d1), "=r"(d2), "=r"(d3) : "r"(a))

#define IMMA(d0, d1, d2, d3, a0, a1, a2, a3, b0, b1)                             \
    asm volatile("mma.sync.aligned.m16n8k32.row.col.s32.s8.s8.s32 "              \
        "{%0,%1,%2,%3}, {%4,%5,%6,%7}, {%8,%9}, {%0,%1,%2,%3};"                  \
        : "+r"(d0), "+r"(d1), "+r"(d2), "+r"(d3)                                 \
        : "r"(a0), "r"(a1), "r"(a2), "r"(a3), "r"(b0), "r"(b1))

// first MMA: C preloaded with h = -round(|c|^2/2) per column
#define IMMA_INIT(d0, d1, d2, d3, a0, a1, a2, a3, b0, b1, c0, c1)                \
    asm volatile("mma.sync.aligned.m16n8k32.row.col.s32.s8.s8.s32 "              \
        "{%0,%1,%2,%3}, {%4,%5,%6,%7}, {%8,%9}, {%10,%11,%12,%13};"              \
        : "=r"(d0), "=r"(d1), "=r"(d2), "=r"(d3)                                 \
        : "r"(a0), "r"(a1), "r"(a2), "r"(a3), "r"(b0), "r"(b1),                  \
          "r"(c0), "r"(c1), "r"(c0), "r"(c1))

#define CP_ASYNC16(dst, src) \
    asm volatile("cp.async.cg.shared.global [%0], [%1], 16;" :: "r"(dst), "l"(src) : "memory")
#define CP_COMMIT() asm volatile("cp.async.commit_group;" ::: "memory")
#define CP_WAIT0()  asm volatile("cp.async.wait_group 0;" ::: "memory")

// ---------------- prepass: quantize codes + h table ----------------
__global__ void prep_codes(const float* __restrict__ codes) {
    int m = blockIdx.x * blockDim.x + threadIdx.x;
    if (m >= M_) return;
    const float4* p = reinterpret_cast<const float4*>(codes + (size_t)m * D_);
    int sv2 = 0;
    uint32_t pk[16];
#pragma unroll
    for (int i = 0; i < 16; i++) {
        float4 v = p[i];
        int i0 = clamp8(v.x), i1 = clamp8(v.y), i2 = clamp8(v.z), i3 = clamp8(v.w);
        sv2 += i0 * i0 + i1 * i1 + i2 * i2 + i3 * i3;
        pk[i] = pack4(i0, i1, i2, i3);
    }
    uint4* dst = reinterpret_cast<uint4*>(g_codes_s8 + (size_t)m * 16);
#pragma unroll
    for (int i = 0; i < 4; i++)
        dst[i] = make_uint4(pk[i * 4], pk[i * 4 + 1], pk[i * 4 + 2], pk[i * 4 + 3]);
    g_hint[m] = -((sv2 + 1) >> 1);
}

// ---------------- main: IMMA GEMM + max-key tracking ----------------
__global__ __launch_bounds__(THREADS, 2) void nn_kernel(
    const float* __restrict__ x, float* __restrict__ out)
{
    // smem: 2 x 16K (s8 B tiles, 256 codes x 64B) + 16K (h) = 48K
    __shared__ __align__(16) char sb[2][TILE_N * 64];
    __shared__ __align__(16) int  sh[M_];

    const int tid  = threadIdx.x;
    const int lane = tid & 31;
    const int wid  = tid >> 5;
    const int wr0  = wid * 32;                // warp owns 32 rows (2 m16 blocks)
    const int row0 = blockIdx.x * TILE_R;

    const uint32_t sbu0 = smem_u32(sb[0]);
    const uint32_t sbu1 = smem_u32(sb[1]);

    // cp.async dst offsets (4 x 16B per thread; row = idx>>2, chunk = idx&3)
    uint32_t cpo[4];
#pragma unroll
    for (int i = 0; i < 4; i++) {
        int idx = tid + i * THREADS;          // 1024 chunks
        cpo[i] = swz64((idx >> 2) * 64 + (idx & 3) * 16);
    }

    // kick off B tile 0
    {
        const char* src = (const char*)g_codes_s8;
#pragma unroll
        for (int i = 0; i < 4; i++)
            CP_ASYNC16(sbu0 + cpo[i], src + (size_t)(tid + i * THREADS) * 16);
        CP_COMMIT();
    }

    // h table -> smem (overlaps cp.async)
#pragma unroll
    for (int j = 0; j < 4; j++) {
        int idx = tid + j * THREADS;          // 1024 int4
        *reinterpret_cast<int4*>(sh + idx * 4) =
            *reinterpret_cast<const int4*>(g_hint + idx * 4);
    }

    // A fragments: quantize x directly from gmem (m16n8k32 s8 A layout)
    uint32_t a[2][8];
#pragma unroll
    for (int blk = 0; blk < 2; blk++) {
        const int rl = row0 + wr0 + blk * 16 + (lane >> 2);
        const float* p0 = x + (size_t)rl * D_;
        const float* p1 = p0 + 8 * D_;        // +8 rows
        const int k0 = (lane & 3) * 4;
#pragma unroll
        for (int c = 0; c < 2; c++) {         // k chunks 0..31 / 32..63
            a[blk][c * 4 + 0] = q4(*reinterpret_cast<const float4*>(p0 + k0 + 32 * c));
            a[blk][c * 4 + 1] = q4(*reinterpret_cast<const float4*>(p1 + k0 + 32 * c));
            a[blk][c * 4 + 2] = q4(*reinterpret_cast<const float4*>(p0 + k0 + 32 * c + 16));
            a[blk][c * 4 + 3] = q4(*reinterpret_cast<const float4*>(p1 + k0 + 32 * c + 16));
        }
    }

    CP_WAIT0();
    __syncthreads();

    // B ldmatrix base (j adds 512B = 8 code rows)
    const uint32_t bo = swz64((lane & 7) * 64 + (lane >> 3) * 16);
    const int cq = (lane & 3) * 2;            // thread's column pair

    // running max of key = sum(u*v) - round(|v|^2/2); min d2 == max key
    int k00 = INT32_MIN, k01 = INT32_MIN, k10 = INT32_MIN, k11 = INT32_MIN;

    for (int t = 0; t < NT; t++) {
        const uint32_t sbu = (t & 1) ? sbu1 : sbu0;

        if (t + 1 < NT) {
            const uint32_t dbu = (t & 1) ? sbu0 : sbu1;
            const char* src = (const char*)g_codes_s8 + ((size_t)(t + 1) << 14);
#pragma unroll
            for (int i = 0; i < 4; i++)
                CP_ASYNC16(dbu + cpo[i], src + (size_t)(tid + i * THREADS) * 16);
            CP_COMMIT();
        }

#pragma unroll
        for (int j = 0; j < TILE_N / 8; j++) {     // 32 n-frags of 8 codes, all K=64 in 1 LDSM
            uint32_t b0, b1, b2, b3;
            LDSM4(b0, b1, b2, b3, sbu + bo + j * 512);

            const int2 hp = *reinterpret_cast<const int2*>(sh + t * TILE_N + j * 8 + cq);

            int d0, d1, d2, d3, e0, e1, e2, e3;
            IMMA_INIT(d0, d1, d2, d3, a[0][0], a[0][1], a[0][2], a[0][3], b0, b1, hp.x, hp.y);
            IMMA_INIT(e0, e1, e2, e3, a[1][0], a[1][1], a[1][2], a[1][3], b0, b1, hp.x, hp.y);
            IMMA(d0, d1, d2, d3, a[0][4], a[0][5], a[0][6], a[0][7], b2, b3);
            IMMA(e0, e1, e2, e3, a[1][4], a[1][5], a[1][6], a[1][7], b2, b3);

            k00 = max(k00, max(d0, d1));      // block0 row g
            k01 = max(k01, max(d2, d3));      // block0 row g+8
            k10 = max(k10, max(e0, e1));      // block1 row g
            k11 = max(k11, max(e2, e3));      // block1 row g+8
        }

        CP_WAIT0();
        __syncthreads();
    }

    // quad reduction (lanes 4q..4q+3 share rows)
#pragma unroll
    for (int off = 1; off <= 2; off <<= 1) {
        k00 = max(k00, __shfl_xor_sync(0xffffffffu, k00, off));
        k01 = max(k01, __shfl_xor_sync(0xffffffffu, k01, off));
        k10 = max(k10, __shfl_xor_sync(0xffffffffu, k10, off));
        k11 = max(k11, __shfl_xor_sync(0xffffffffu, k11, off));
    }

    if ((lane & 3) == 0) {
        const int keys[4] = { k00, k01, k10, k11 };
        const int rows[4] = { wr0 + (lane >> 2),      wr0 + (lane >> 2) + 8,
                              wr0 + (lane >> 2) + 16, wr0 + (lane >> 2) + 24 };
#pragma unroll
        for (int v = 0; v < 4; v++) {
            const int row = row0 + rows[v];
            const float* xr = x + (size_t)row * D_;
            float x2q = 0.f;                   // sum of quantized u^2 (u-units)
#pragma unroll
            for (int i = 0; i < 16; i++) {
                float4 u = *reinterpret_cast<const float4*>(xr + i * 4);
                float q0 = fminf(127.f, fmaxf(-127.f, rintf(u.x * QSCALE)));
                float q1 = fminf(127.f, fmaxf(-127.f, rintf(u.y * QSCALE)));
                float q2 = fminf(127.f, fmaxf(-127.f, rintf(u.z * QSCALE)));
                float q3 = fminf(127.f, fmaxf(-127.f, rintf(u.w * QSCALE)));
                x2q = fmaf(q0, q0, x2q); x2q = fmaf(q1, q1, x2q);
                x2q = fmaf(q2, q2, x2q); x2q = fmaf(q3, q3, x2q);
            }
            // d2_est = (sum u^2 - 2*key)/s^2  (key exact s32; |key| < 2^24)
            float d2e = (x2q - 2.f * (float)keys[v]) * (1.f / (QSCALE * QSCALE));
            if (d2e > FILTER) { out[row] = -1.0f; g_need[row] = 0; }
            else              { g_need[row] = 1; }
        }
    }
}

// ---------------- exact fallback for flagged rows (reference semantics) ----------------
__global__ void nn_exact(const float* __restrict__ x, const float* __restrict__ codes,
                         float* __restrict__ out)
{
    int row = blockIdx.x * blockDim.x + threadIdx.x;
    if (row >= ROWS_ || !g_need[row]) return;

    float xr[D_];
    const float4* xp = reinterpret_cast<const float4*>(x + (size_t)row * D_);
#pragma unroll
    for (int i = 0; i < 16; i++) {
        float4 v = xp[i];
        xr[i * 4] = v.x; xr[i * 4 + 1] = v.y; xr[i * 4 + 2] = v.z; xr[i * 4 + 3] = v.w;
    }
    float best = 3.4e38f;
    int   bi   = 0;
    for (int m = 0; m < M_; m++) {
        const float4* cp = reinterpret_cast<const float4*>(codes + (size_t)m * D_);
        float d2 = 0.f;
#pragma unroll
        for (int i = 0; i < 16; i++) {
            float4 c = cp[i];
            float t0 = xr[i * 4] - c.x, t1 = xr[i * 4 + 1] - c.y;
            float t2 = xr[i * 4 + 2] - c.z, t3 = xr[i * 4 + 3] - c.w;
            d2 = fmaf(t0, t0, d2); d2 = fmaf(t1, t1, d2);
            d2 = fmaf(t2, t2, d2); d2 = fmaf(t3, t3, d2);
        }
        if (d2 < best) { best = d2; bi = m; }   // strict '<': first occurrence
    }
    out[row] = (best <= 0.1f) ? (float)bi : -1.0f;
}

extern "C" void kernel_launch(void* const* d_in, const int* in_sizes, int n_in,
                              void* d_out, int out_size) {
    const float* x     = (const float*)d_in[0];  // [16,4096,64] f32
    const float* codes = (const float*)d_in[1];  // [4096,64]    f32
    float* out = (float*)d_out;                  // [16,4096]    f32

    (void)in_sizes; (void)n_in; (void)out_size;

    prep_codes<<<M_ / 256, 256>>>(codes);
    nn_kernel<<<ROWS_ / TILE_R, THREADS>>>(x, out);
    nn_exact<<<ROWS_ / 256, 256>>>(x, codes, out);
}